// round 3
// baseline (speedup 1.0000x reference)
#include <cuda_runtime.h>
#include <cstdint>

#define N_NODES 100000
#define N_EDGES 1600000
#define C 32

// Scratch (device globals; zero-initialized at module load).
// g_degi is left zeroed at the end of every kernel_launch call (k_gemm
// zeroes it after consuming), so the histogram restarts correctly on
// every graph replay.
__device__ int   g_degi[N_NODES];
__device__ float g_dinv[N_NODES];
__device__ float g_hs[N_NODES * C];   // hs[i] = (x[i] @ W^T) * dinv[i]

// ---------------------------------------------------------------------------
// K1: in-degree histogram over targets (4 edges per thread, vectorized load)
__global__ void k_count(const int* __restrict__ col) {
    int t = blockIdx.x * blockDim.x + threadIdx.x;
    int e4 = t * 4;
    if (e4 + 3 < N_EDGES) {
        int4 c = *reinterpret_cast<const int4*>(col + e4);
        atomicAdd(&g_degi[c.x], 1);
        atomicAdd(&g_degi[c.y], 1);
        atomicAdd(&g_degi[c.z], 1);
        atomicAdd(&g_degi[c.w], 1);
    } else {
        for (int e = e4; e < N_EDGES; e++) atomicAdd(&g_degi[col[e]], 1);
    }
}

// K2: dinv = rsqrt(deg+1); hs = (x @ W^T) * dinv; out = hs*dinv + b
//     Also re-zeroes g_degi for the next call. Block = 8 nodes x 32 channels.
__global__ void k_gemm(const float* __restrict__ x,
                       const float* __restrict__ W,
                       const float* __restrict__ b,
                       float* __restrict__ out) {
    __shared__ float Wsh[C][C + 1];   // Wsh[k][co] = W[co*C + k]
    int tid = threadIdx.x;
    #pragma unroll
    for (int i = tid; i < C * C; i += 256) {
        Wsh[i % C][i / C] = W[i];
    }
    __syncthreads();

    int n  = blockIdx.x * 8 + (tid >> 5);
    int co = tid & 31;
    if (n >= N_NODES) return;

    int deg = g_degi[n];
    if (co == 0) g_degi[n] = 0;                    // reset for next launch
    float dinv = rsqrtf((float)(deg + 1));         // +1 = self loop
    if (co == 0) g_dinv[n] = dinv;

    const float* xr = x + n * C;
    float acc = 0.0f;
    #pragma unroll
    for (int k = 0; k < C; k++) acc += __ldg(xr + k) * Wsh[k][co];

    float hs = acc * dinv;
    g_hs[n * C + co] = hs;
    out[n * C + co] = fmaf(hs, dinv, __ldg(b + co));   // self-loop + bias
}

// K3: edge scatter — out[col] += hs[row] * dinv[col], vector f32x4 RED.
//     8 threads per edge-slot, each thread handles 2 edges (better MLP).
__global__ void k_scatter(const int* __restrict__ rowv,
                          const int* __restrict__ colv,
                          float* __restrict__ out) {
    int t = blockIdx.x * blockDim.x + threadIdx.x;
    int e0 = (t >> 3) * 2;
    int g  = t & 7;
    if (e0 >= N_EDGES) return;

    int r0 = __ldg(rowv + e0);
    int c0 = __ldg(colv + e0);
    int r1 = __ldg(rowv + e0 + 1);
    int c1 = __ldg(colv + e0 + 1);

    float4 v0 = *reinterpret_cast<const float4*>(g_hs + r0 * C + g * 4);
    float  d0 = __ldg(g_dinv + c0);
    float4 v1 = *reinterpret_cast<const float4*>(g_hs + r1 * C + g * 4);
    float  d1 = __ldg(g_dinv + c1);

    float* dst0 = out + (size_t)c0 * C + g * 4;
    asm volatile("red.global.add.v4.f32 [%0], {%1, %2, %3, %4};"
                 :: "l"(dst0), "f"(v0.x * d0), "f"(v0.y * d0),
                    "f"(v0.z * d0), "f"(v0.w * d0) : "memory");

    float* dst1 = out + (size_t)c1 * C + g * 4;
    asm volatile("red.global.add.v4.f32 [%0], {%1, %2, %3, %4};"
                 :: "l"(dst1), "f"(v1.x * d1), "f"(v1.y * d1),
                    "f"(v1.z * d1), "f"(v1.w * d1) : "memory");
}

// ---------------------------------------------------------------------------
extern "C" void kernel_launch(void* const* d_in, const int* in_sizes, int n_in,
                              void* d_out, int out_size) {
    const float* x  = (const float*)d_in[0];
    const int*   ei = (const int*)d_in[1];    // [2, E]: row then col
    const float* W  = (const float*)d_in[2];
    const float* b  = (const float*)d_in[3];
    float* out = (float*)d_out;

    const int* rowv = ei;
    const int* colv = ei + N_EDGES;

    k_count<<<(N_EDGES / 4 + 255) / 256, 256>>>(colv);
    k_gemm<<<(N_NODES + 7) / 8, 256>>>(x, W, b, out);
    // N_EDGES/2 edge-pairs * 8 threads each = N_EDGES*4 threads
    k_scatter<<<(N_EDGES * 4 + 255) / 256, 256>>>(rowv, colv, out);
}